// round 2
// baseline (speedup 1.0000x reference)
#include <cuda_runtime.h>

#define NCONE 8
#define NDIM 24          // 3 * NCONE
#define NITERS 100
#define BATCH 65536
#define POWER_ITERS 400
#define TPB 64           // threads per block

// ---------------------------------------------------------------------------
// Device globals (no allocation allowed)
// ---------------------------------------------------------------------------
__device__ float g_A[NDIM * NDIM];   // A = I - step * P   (row k, col j)
__device__ float g_step;

// ---------------------------------------------------------------------------
// Packed f32x2 helpers (Blackwell fma.rn.f32x2)
// ---------------------------------------------------------------------------
__device__ __forceinline__ unsigned long long pack2(float a, float b) {
    unsigned long long r;
    asm("mov.b64 %0, {%1, %2};" : "=l"(r) : "f"(a), "f"(b));
    return r;
}
__device__ __forceinline__ void unpack2(unsigned long long v, float& a, float& b) {
    asm("mov.b64 {%0, %1}, %2;" : "=f"(a), "=f"(b) : "l"(v));
}
__device__ __forceinline__ unsigned long long fma2(unsigned long long a,
                                                   unsigned long long b,
                                                   unsigned long long c) {
    unsigned long long d;
    asm("fma.rn.f32x2 %0, %1, %2, %3;" : "=l"(d) : "l"(a), "l"(b), "l"(c));
    return d;
}
__device__ __forceinline__ float fsqrt_ap(float x) {
    float r; asm("sqrt.approx.f32 %0, %1;" : "=f"(r) : "f"(x)); return r;
}
__device__ __forceinline__ float frcp_ap(float x) {
    float r; asm("rcp.approx.f32 %0, %1;" : "=f"(r) : "f"(x)); return r;
}

// ---------------------------------------------------------------------------
// Prep: power iteration for lambda_max(P), then A = I - (1/L) P.
// One warp; deterministic.
// ---------------------------------------------------------------------------
__global__ void prep_kernel(const float* __restrict__ P) {
    __shared__ float Ps[NDIM * NDIM];
    __shared__ float v[NDIM];
    __shared__ float w[NDIM];
    const int t = threadIdx.x;

    for (int i = t; i < NDIM * NDIM; i += 32) Ps[i] = P[i];
    if (t < NDIM) v[t] = 1.0f;
    __syncthreads();

    for (int it = 0; it < POWER_ITERS; it++) {
        float s = 0.0f;
        if (t < NDIM) {
            #pragma unroll
            for (int k = 0; k < NDIM; k++) s += Ps[t * NDIM + k] * v[k];
            w[t] = s;
        }
        __syncthreads();
        float sq = (t < NDIM) ? w[t] * w[t] : 0.0f;
        #pragma unroll
        for (int off = 16; off > 0; off >>= 1)
            sq += __shfl_xor_sync(0xffffffffu, sq, off);
        float rinv = rsqrtf(sq);
        if (t < NDIM) v[t] = w[t] * rinv;
        __syncthreads();
    }

    float s = 0.0f;
    if (t < NDIM) {
        #pragma unroll
        for (int k = 0; k < NDIM; k++) s += Ps[t * NDIM + k] * v[k];
    }
    float num = (t < NDIM) ? v[t] * s : 0.0f;
    float den = (t < NDIM) ? v[t] * v[t] : 0.0f;
    #pragma unroll
    for (int off = 16; off > 0; off >>= 1) {
        num += __shfl_xor_sync(0xffffffffu, num, off);
        den += __shfl_xor_sync(0xffffffffu, den, off);
    }
    const float step = den / num;  // 1 / lambda_max
    if (t == 0) g_step = step;

    for (int i = t; i < NDIM * NDIM; i += 32) {
        int r = i / NDIM, c = i % NDIM;
        g_A[i] = ((r == c) ? 1.0f : 0.0f) - step * Ps[i];
    }
}

// ---------------------------------------------------------------------------
// Solver: one thread per batch row; l[24] in registers for 100 iterations.
// A (uniform) in shared; b = -step*q in shared as f32x2 pairs, transposed
// layout [pair][thread] -> conflict-free LDS.64 replacing acc init.
// ---------------------------------------------------------------------------
__global__ void __launch_bounds__(TPB, 8)
solve_kernel(const float* __restrict__ q, float* __restrict__ out) {
    __shared__ __align__(16) float Ash[NDIM][NDIM];
    __shared__ unsigned long long Bsh[12][TPB];

    const int tid = threadIdx.x;
    const int row = blockIdx.x * TPB + tid;

    for (int i = tid; i < NDIM * NDIM; i += TPB)
        (&Ash[0][0])[i] = g_A[i];

    // b = -step * q[row], stored as 12 packed pairs in shared
    {
        const float stepv = g_step;
        const float4* q4 = reinterpret_cast<const float4*>(q + (size_t)row * NDIM);
        #pragma unroll
        for (int i = 0; i < 6; i++) {
            float4 v = q4[i];
            Bsh[2 * i + 0][tid] = pack2(-stepv * v.x, -stepv * v.y);
            Bsh[2 * i + 1][tid] = pack2(-stepv * v.z, -stepv * v.w);
        }
    }
    __syncthreads();

    float l[NDIM];
    #pragma unroll
    for (int j = 0; j < NDIM; j++) l[j] = 0.0f;

    #pragma unroll 1
    for (int it = 0; it < NITERS; it++) {
        // acc = b  (12 x LDS.64, conflict-free)
        unsigned long long acc[12];
        #pragma unroll
        for (int jp = 0; jp < 12; jp++) acc[jp] = Bsh[jp][tid];

        // y = l @ A + b : per k-row, 6 x LDS.128 (broadcast) + 12 FFMA2
        #pragma unroll
        for (int k = 0; k < NDIM; k++) {
            const unsigned long long lk = pack2(l[k], l[k]);
            const ulonglong2* rp = reinterpret_cast<const ulonglong2*>(&Ash[k][0]);
            #pragma unroll
            for (int m = 0; m < 6; m++) {
                ulonglong2 p = rp[m];
                acc[2 * m + 0] = fma2(lk, p.x, acc[2 * m + 0]);
                acc[2 * m + 1] = fma2(lk, p.y, acc[2 * m + 1]);
            }
        }

        // Branch-free SOC projection, 8 cones:
        //   t = y[i], x = (y[8+2i], y[9+2i]) = both halves of acc[4+i]
        //   s = saturate(0.5 + 0.5*t/n);  x *= s;  t_new = (n<=t) ? t : s*n
        #pragma unroll
        for (int i = 0; i < NCONE; i++) {
            float ta, tb;
            unpack2(acc[i >> 1], ta, tb);
            float t = (i & 1) ? tb : ta;
            float x0, x1;
            unpack2(acc[4 + i], x0, x1);
            float nsq = fmaf(x1, x1, x0 * x0);
            float n   = fsqrt_ap(nsq);           // sqrt.approx(0) = 0
            float rn  = frcp_ap(n);              // rcp.approx(0) = +inf
            float u   = fmaf(0.5f * t, rn, 0.5f);
            float s   = __saturatef(u);          // saturate(NaN) = 0
            bool inside = (n <= t);
            float sn  = s * n;
            l[i]             = inside ? t : sn;
            l[NCONE + 2 * i + 0] = x0 * s;
            l[NCONE + 2 * i + 1] = x1 * s;
        }
    }

    float4* o4 = reinterpret_cast<float4*>(out + (size_t)row * NDIM);
    #pragma unroll
    for (int i = 0; i < 6; i++)
        o4[i] = make_float4(l[4 * i + 0], l[4 * i + 1], l[4 * i + 2], l[4 * i + 3]);
}

// ---------------------------------------------------------------------------
// Entry point
// ---------------------------------------------------------------------------
extern "C" void kernel_launch(void* const* d_in, const int* in_sizes, int n_in,
                              void* d_out, int out_size) {
    const float* P = (const float*)d_in[0];   // (1, 24, 24) fp32
    const float* q = (const float*)d_in[1];   // (65536, 24, 1) fp32
    float* out = (float*)d_out;               // (65536, 24) fp32

    prep_kernel<<<1, 32>>>(P);
    solve_kernel<<<BATCH / TPB, TPB>>>(q, out);
}

// round 3
// speedup vs baseline: 6.4962x; 6.4962x over previous
#include <cuda_runtime.h>

#define NCONE 8
#define NDIM 24          // 3 * NCONE
#define NITERS 100
#define BATCH 65536
#define POWER_ITERS 400
#define TPB 64

// ---------------------------------------------------------------------------
// Globals (no dynamic allocation anywhere)
// ---------------------------------------------------------------------------
__device__ float g_A[NDIM * NDIM];       // prep output: A = I - step*P
__device__ float g_step;
__constant__ float c_A[NDIM * NDIM];     // solver reads A via constant cache

// ---------------------------------------------------------------------------
// Packed f32x2 helpers
// ---------------------------------------------------------------------------
__device__ __forceinline__ unsigned long long pack2(float a, float b) {
    unsigned long long r;
    asm("mov.b64 %0, {%1, %2};" : "=l"(r) : "f"(a), "f"(b));
    return r;
}
__device__ __forceinline__ void unpack2(unsigned long long v, float& a, float& b) {
    asm("mov.b64 {%0, %1}, %2;" : "=f"(a), "=f"(b) : "l"(v));
}
__device__ __forceinline__ unsigned long long fma2(unsigned long long a,
                                                   unsigned long long b,
                                                   unsigned long long c) {
    unsigned long long d;
    asm("fma.rn.f32x2 %0, %1, %2, %3;" : "=l"(d) : "l"(a), "l"(b), "l"(c));
    return d;
}
__device__ __forceinline__ float fsqrt_ap(float x) {
    float r; asm("sqrt.approx.f32 %0, %1;" : "=f"(r) : "f"(x)); return r;
}
__device__ __forceinline__ float frcp_ap(float x) {
    float r; asm("rcp.approx.f32 %0, %1;" : "=f"(r) : "f"(x)); return r;
}

// ---------------------------------------------------------------------------
// Prep: power iteration for lambda_max(P); writes g_A = I - (1/L) P, g_step.
// ---------------------------------------------------------------------------
__global__ void prep_kernel(const float* __restrict__ P) {
    __shared__ float Ps[NDIM * NDIM];
    __shared__ float v[NDIM];
    __shared__ float w[NDIM];
    const int t = threadIdx.x;

    for (int i = t; i < NDIM * NDIM; i += 32) Ps[i] = P[i];
    if (t < NDIM) v[t] = 1.0f;
    __syncthreads();

    for (int it = 0; it < POWER_ITERS; it++) {
        float s = 0.0f;
        if (t < NDIM) {
            #pragma unroll
            for (int k = 0; k < NDIM; k++) s += Ps[t * NDIM + k] * v[k];
            w[t] = s;
        }
        __syncthreads();
        float sq = (t < NDIM) ? w[t] * w[t] : 0.0f;
        #pragma unroll
        for (int off = 16; off > 0; off >>= 1)
            sq += __shfl_xor_sync(0xffffffffu, sq, off);
        float rinv = rsqrtf(sq);
        if (t < NDIM) v[t] = w[t] * rinv;
        __syncthreads();
    }

    float s = 0.0f;
    if (t < NDIM) {
        #pragma unroll
        for (int k = 0; k < NDIM; k++) s += Ps[t * NDIM + k] * v[k];
    }
    float num = (t < NDIM) ? v[t] * s : 0.0f;
    float den = (t < NDIM) ? v[t] * v[t] : 0.0f;
    #pragma unroll
    for (int off = 16; off > 0; off >>= 1) {
        num += __shfl_xor_sync(0xffffffffu, num, off);
        den += __shfl_xor_sync(0xffffffffu, den, off);
    }
    const float step = den / num;  // 1 / lambda_max
    if (t == 0) g_step = step;

    for (int i = t; i < NDIM * NDIM; i += 32) {
        int r = i / NDIM, c = i % NDIM;
        g_A[i] = ((r == c) ? 1.0f : 0.0f) - step * Ps[i];
    }
}

// ---------------------------------------------------------------------------
// Solver: one thread per row. A read from __constant__ (uniform datapath,
// no smem crossbar traffic). b = -step*q kept in shared (conflict-free).
// l[24] + acc[12 packed] in registers.
// ---------------------------------------------------------------------------
__global__ void __launch_bounds__(TPB, 10)
solve_kernel(const float* __restrict__ q, float* __restrict__ out) {
    __shared__ unsigned long long Bsh[12][TPB];

    const int tid = threadIdx.x;
    const int row = blockIdx.x * TPB + tid;

    {
        const float stepv = g_step;
        const float4* q4 = reinterpret_cast<const float4*>(q + (size_t)row * NDIM);
        #pragma unroll
        for (int i = 0; i < 6; i++) {
            float4 v = q4[i];
            Bsh[2 * i + 0][tid] = pack2(-stepv * v.x, -stepv * v.y);
            Bsh[2 * i + 1][tid] = pack2(-stepv * v.z, -stepv * v.w);
        }
    }
    __syncthreads();

    float l[NDIM];
    #pragma unroll
    for (int j = 0; j < NDIM; j++) l[j] = 0.0f;

    #pragma unroll 1
    for (int it = 0; it < NITERS; it++) {
        unsigned long long acc[12];
        #pragma unroll
        for (int jp = 0; jp < 12; jp++) acc[jp] = Bsh[jp][tid];

        // y = l @ A + b ; A from constant memory, compile-time indices
        #pragma unroll
        for (int k = 0; k < NDIM; k++) {
            const unsigned long long lk = pack2(l[k], l[k]);
            const float4* Ar = reinterpret_cast<const float4*>(&c_A[k * NDIM]);
            #pragma unroll
            for (int m = 0; m < 6; m++) {
                float4 a = Ar[m];
                acc[2 * m + 0] = fma2(lk, pack2(a.x, a.y), acc[2 * m + 0]);
                acc[2 * m + 1] = fma2(lk, pack2(a.z, a.w), acc[2 * m + 1]);
            }
        }

        // Branch-free SOC projection, 8 cones
        #pragma unroll
        for (int i = 0; i < NCONE; i++) {
            float ta, tb;
            unpack2(acc[i >> 1], ta, tb);
            float t = (i & 1) ? tb : ta;
            float x0, x1;
            unpack2(acc[4 + i], x0, x1);
            float nsq = fmaf(x1, x1, x0 * x0);
            float n   = fsqrt_ap(nsq);
            float rn  = frcp_ap(n);
            float u   = fmaf(0.5f * t, rn, 0.5f);
            float s   = __saturatef(u);      // saturate(NaN)=0 handles n==0
            bool inside = (n <= t);
            float sn  = s * n;
            l[i]                 = inside ? t : sn;
            l[NCONE + 2 * i + 0] = x0 * s;
            l[NCONE + 2 * i + 1] = x1 * s;
        }
    }

    float4* o4 = reinterpret_cast<float4*>(out + (size_t)row * NDIM);
    #pragma unroll
    for (int i = 0; i < 6; i++)
        o4[i] = make_float4(l[4 * i + 0], l[4 * i + 1], l[4 * i + 2], l[4 * i + 3]);
}

// ---------------------------------------------------------------------------
// Entry point (graph-capturable: kernels + D2D memcpy only)
// ---------------------------------------------------------------------------
extern "C" void kernel_launch(void* const* d_in, const int* in_sizes, int n_in,
                              void* d_out, int out_size) {
    const float* P = (const float*)d_in[0];   // (1, 24, 24) fp32
    const float* q = (const float*)d_in[1];   // (65536, 24, 1) fp32
    float* out = (float*)d_out;               // (65536, 24) fp32

    prep_kernel<<<1, 32>>>(P);

    void* gA_ptr = nullptr;
    cudaGetSymbolAddress(&gA_ptr, g_A);
    cudaMemcpyToSymbolAsync(c_A, gA_ptr, NDIM * NDIM * sizeof(float), 0,
                            cudaMemcpyDeviceToDevice, 0);

    solve_kernel<<<BATCH / TPB, TPB>>>(q, out);
}

// round 4
// speedup vs baseline: 7.9461x; 1.2232x over previous
#include <cuda_runtime.h>

#define NCONE 8
#define NDIM 24          // 3 * NCONE
#define NITERS 100
#define BATCH 65536
#define POWER_ITERS 256  // normalize every 16
#define TPB 32

// ---------------------------------------------------------------------------
// Globals (no dynamic allocation anywhere)
// ---------------------------------------------------------------------------
__device__ float g_A[NDIM * NDIM];       // prep output: A = I - step*P
__device__ float g_step;
__constant__ float c_A[NDIM * NDIM];     // solver reads A via constant cache

// ---------------------------------------------------------------------------
// Packed f32x2 helpers
// ---------------------------------------------------------------------------
__device__ __forceinline__ unsigned long long pack2(float a, float b) {
    unsigned long long r;
    asm("mov.b64 %0, {%1, %2};" : "=l"(r) : "f"(a), "f"(b));
    return r;
}
__device__ __forceinline__ void unpack2(unsigned long long v, float& a, float& b) {
    asm("mov.b64 {%0, %1}, %2;" : "=f"(a), "=f"(b) : "l"(v));
}
__device__ __forceinline__ unsigned long long fma2(unsigned long long a,
                                                   unsigned long long b,
                                                   unsigned long long c) {
    unsigned long long d;
    asm("fma.rn.f32x2 %0, %1, %2, %3;" : "=l"(d) : "l"(a), "l"(b), "l"(c));
    return d;
}
__device__ __forceinline__ float fsqrt_ap(float x) {
    float r; asm("sqrt.approx.f32 %0, %1;" : "=f"(r) : "f"(x)); return r;
}
__device__ __forceinline__ float frcp_ap(float x) {
    float r; asm("rcp.approx.f32 %0, %1;" : "=f"(r) : "f"(x)); return r;
}

// ---------------------------------------------------------------------------
// Prep: power iteration for lambda_max(P); A = I - (1/L) P.
// One warp. 4-way split accumulators shorten the matvec chain; norm applied
// every 16 iters only (values grow <= lam^16 ~ 3e10, safe in fp32; Rayleigh
// quotient at the end is scale-invariant).
// ---------------------------------------------------------------------------
__global__ void prep_kernel(const float* __restrict__ P) {
    __shared__ float Ps[NDIM * NDIM];
    __shared__ float v[NDIM];
    __shared__ float w[NDIM];
    const int t = threadIdx.x;

    for (int i = t; i < NDIM * NDIM; i += 32) Ps[i] = P[i];
    if (t < NDIM) v[t] = 1.0f;
    __syncthreads();

    for (int it = 0; it < POWER_ITERS; it++) {
        if (t < NDIM) {
            float s0 = 0.f, s1 = 0.f, s2 = 0.f, s3 = 0.f;
            const float* Pr = &Ps[t * NDIM];
            #pragma unroll
            for (int k = 0; k < 6; k++) {
                s0 = fmaf(Pr[4 * k + 0], v[4 * k + 0], s0);
                s1 = fmaf(Pr[4 * k + 1], v[4 * k + 1], s1);
                s2 = fmaf(Pr[4 * k + 2], v[4 * k + 2], s2);
                s3 = fmaf(Pr[4 * k + 3], v[4 * k + 3], s3);
            }
            w[t] = (s0 + s1) + (s2 + s3);
        }
        __syncthreads();
        if ((it & 15) == 15) {
            float sq = (t < NDIM) ? w[t] * w[t] : 0.0f;
            #pragma unroll
            for (int off = 16; off > 0; off >>= 1)
                sq += __shfl_xor_sync(0xffffffffu, sq, off);
            float rinv = rsqrtf(sq);
            if (t < NDIM) v[t] = w[t] * rinv;
        } else {
            if (t < NDIM) v[t] = w[t];
        }
        __syncthreads();
    }

    // Rayleigh quotient (scale-invariant): lam = (v^T P v) / (v^T v)
    float s = 0.0f;
    if (t < NDIM) {
        #pragma unroll
        for (int k = 0; k < NDIM; k++) s += Ps[t * NDIM + k] * v[k];
    }
    float num = (t < NDIM) ? v[t] * s : 0.0f;
    float den = (t < NDIM) ? v[t] * v[t] : 0.0f;
    #pragma unroll
    for (int off = 16; off > 0; off >>= 1) {
        num += __shfl_xor_sync(0xffffffffu, num, off);
        den += __shfl_xor_sync(0xffffffffu, den, off);
    }
    const float step = den / num;  // 1 / lambda_max
    if (t == 0) g_step = step;

    for (int i = t; i < NDIM * NDIM; i += 32) {
        int r = i / NDIM, c = i % NDIM;
        g_A[i] = ((r == c) ? 1.0f : 0.0f) - step * Ps[i];
    }
}

// ---------------------------------------------------------------------------
// Solver: one thread per row, single-warp CTAs, zero shared memory.
// A from __constant__; b = -step*q held in registers; acc init folded into
// the k=0 FFMA2s. l[24] in registers for all 100 iterations.
// ---------------------------------------------------------------------------
__global__ void __launch_bounds__(TPB, 16)
solve_kernel(const float* __restrict__ q, float* __restrict__ out) {
    const int row = blockIdx.x * TPB + threadIdx.x;
    const float stepv = g_step;

    // b = -step * q[row] as 12 packed pairs (registers)
    unsigned long long b2[12];
    {
        const float4* q4 = reinterpret_cast<const float4*>(q + (size_t)row * NDIM);
        #pragma unroll
        for (int i = 0; i < 6; i++) {
            float4 v = q4[i];
            b2[2 * i + 0] = pack2(-stepv * v.x, -stepv * v.y);
            b2[2 * i + 1] = pack2(-stepv * v.z, -stepv * v.w);
        }
    }

    float l[NDIM];
    #pragma unroll
    for (int j = 0; j < NDIM; j++) l[j] = 0.0f;

    #pragma unroll 1
    for (int it = 0; it < NITERS; it++) {
        // y = l @ A + b ; k=0 folds the init (acc = l0*A0 + b)
        unsigned long long acc[12];
        {
            const unsigned long long lk = pack2(l[0], l[0]);
            const float4* Ar = reinterpret_cast<const float4*>(&c_A[0]);
            #pragma unroll
            for (int m = 0; m < 6; m++) {
                float4 a = Ar[m];
                acc[2 * m + 0] = fma2(lk, pack2(a.x, a.y), b2[2 * m + 0]);
                acc[2 * m + 1] = fma2(lk, pack2(a.z, a.w), b2[2 * m + 1]);
            }
        }
        #pragma unroll
        for (int k = 1; k < NDIM; k++) {
            const unsigned long long lk = pack2(l[k], l[k]);
            const float4* Ar = reinterpret_cast<const float4*>(&c_A[k * NDIM]);
            #pragma unroll
            for (int m = 0; m < 6; m++) {
                float4 a = Ar[m];
                acc[2 * m + 0] = fma2(lk, pack2(a.x, a.y), acc[2 * m + 0]);
                acc[2 * m + 1] = fma2(lk, pack2(a.z, a.w), acc[2 * m + 1]);
            }
        }

        // Branch-free SOC projection, 8 cones:
        //   s = saturate(0.5 + 0.5*t/n); x *= s; t_new = (n<=t) ? t : s*n
        #pragma unroll
        for (int i = 0; i < NCONE; i++) {
            float ta, tb;
            unpack2(acc[i >> 1], ta, tb);
            float t = (i & 1) ? tb : ta;
            float x0, x1;
            unpack2(acc[4 + i], x0, x1);
            float nsq = fmaf(x1, x1, x0 * x0);
            float n   = fsqrt_ap(nsq);
            float rn  = frcp_ap(n);
            float u   = fmaf(0.5f * t, rn, 0.5f);
            float s   = __saturatef(u);      // saturate(NaN)=0 handles n==0
            bool inside = (n <= t);
            float sn  = s * n;
            l[i]                 = inside ? t : sn;
            l[NCONE + 2 * i + 0] = x0 * s;
            l[NCONE + 2 * i + 1] = x1 * s;
        }
    }

    float4* o4 = reinterpret_cast<float4*>(out + (size_t)row * NDIM);
    #pragma unroll
    for (int i = 0; i < 6; i++)
        o4[i] = make_float4(l[4 * i + 0], l[4 * i + 1], l[4 * i + 2], l[4 * i + 3]);
}

// ---------------------------------------------------------------------------
// Entry point (graph-capturable: kernels + D2D memcpy only)
// ---------------------------------------------------------------------------
extern "C" void kernel_launch(void* const* d_in, const int* in_sizes, int n_in,
                              void* d_out, int out_size) {
    const float* P = (const float*)d_in[0];   // (1, 24, 24) fp32
    const float* q = (const float*)d_in[1];   // (65536, 24, 1) fp32
    float* out = (float*)d_out;               // (65536, 24) fp32

    prep_kernel<<<1, 32>>>(P);

    void* gA_ptr = nullptr;
    cudaGetSymbolAddress(&gA_ptr, g_A);
    cudaMemcpyToSymbolAsync(c_A, gA_ptr, NDIM * NDIM * sizeof(float), 0,
                            cudaMemcpyDeviceToDevice, 0);

    solve_kernel<<<BATCH / TPB, TPB>>>(q, out);
}

// round 5
// speedup vs baseline: 10.0497x; 1.2647x over previous
#include <cuda_runtime.h>

#define NCONE 8
#define NDIM 24          // 3 * NCONE
#define NITERS 100
#define BATCH 65536
#define POWER_ITERS 128  // normalize every 16
#define TPB 32
#define RPT 2            // rows per thread

// ---------------------------------------------------------------------------
// Globals (no dynamic allocation anywhere)
// ---------------------------------------------------------------------------
__device__ float g_A[NDIM * NDIM];       // prep output: A = I - step*P
__device__ float g_step;
__constant__ float c_A[NDIM * NDIM];     // solver reads A via constant cache

// ---------------------------------------------------------------------------
// Helpers
// ---------------------------------------------------------------------------
__device__ __forceinline__ unsigned long long pack2(float a, float b) {
    unsigned long long r;
    asm("mov.b64 %0, {%1, %2};" : "=l"(r) : "f"(a), "f"(b));
    return r;
}
__device__ __forceinline__ void unpack2(unsigned long long v, float& a, float& b) {
    asm("mov.b64 {%0, %1}, %2;" : "=f"(a), "=f"(b) : "l"(v));
}
__device__ __forceinline__ unsigned long long fma2(unsigned long long a,
                                                   unsigned long long b,
                                                   unsigned long long c) {
    unsigned long long d;
    asm("fma.rn.f32x2 %0, %1, %2, %3;" : "=l"(d) : "l"(a), "l"(b), "l"(c));
    return d;
}
__device__ __forceinline__ float frsqrt_ap(float x) {
    float r; asm("rsqrt.approx.f32 %0, %1;" : "=f"(r) : "f"(x)); return r;
}

// Branch-free SOC projection of y (12 packed pairs) into l[24].
// Single MUFU per cone: r = rsqrt(nsq); n = nsq*r; 1/n == r.
//   s = saturate(0.5 + 0.5*t*r); x *= s; t_new = (n<=t) ? t : s*n
// Edge nsq==0: r=rsqrt(1e-30) finite, n=0; t>=0 -> keep t, t<0 -> 0.  Matches ref.
__device__ __forceinline__ void proj_soc(const unsigned long long* acc, float* l) {
    #pragma unroll
    for (int i = 0; i < NCONE; i++) {
        float ta, tb;
        unpack2(acc[i >> 1], ta, tb);
        float t = (i & 1) ? tb : ta;
        float x0, x1;
        unpack2(acc[4 + i], x0, x1);
        float nsq = fmaf(x1, x1, x0 * x0);
        float r   = frsqrt_ap(fmaxf(nsq, 1e-30f));
        float n   = nsq * r;
        float s   = __saturatef(fmaf(0.5f * t, r, 0.5f));
        bool inside = (n <= t);
        float sn  = s * n;
        l[i]                 = inside ? t : sn;
        l[NCONE + 2 * i + 0] = x0 * s;
        l[NCONE + 2 * i + 1] = x1 * s;
    }
}

// ---------------------------------------------------------------------------
// Prep: power iteration for lambda_max(P); A = I - (1/L) P.  One warp.
// ---------------------------------------------------------------------------
__global__ void prep_kernel(const float* __restrict__ P) {
    __shared__ float Ps[NDIM * NDIM];
    __shared__ float v[NDIM];
    __shared__ float w[NDIM];
    const int t = threadIdx.x;

    for (int i = t; i < NDIM * NDIM; i += 32) Ps[i] = P[i];
    if (t < NDIM) v[t] = 1.0f;
    __syncthreads();

    for (int it = 0; it < POWER_ITERS; it++) {
        if (t < NDIM) {
            float s0 = 0.f, s1 = 0.f, s2 = 0.f, s3 = 0.f;
            const float* Pr = &Ps[t * NDIM];
            #pragma unroll
            for (int k = 0; k < 6; k++) {
                s0 = fmaf(Pr[4 * k + 0], v[4 * k + 0], s0);
                s1 = fmaf(Pr[4 * k + 1], v[4 * k + 1], s1);
                s2 = fmaf(Pr[4 * k + 2], v[4 * k + 2], s2);
                s3 = fmaf(Pr[4 * k + 3], v[4 * k + 3], s3);
            }
            w[t] = (s0 + s1) + (s2 + s3);
        }
        __syncthreads();
        if ((it & 15) == 15) {
            float sq = (t < NDIM) ? w[t] * w[t] : 0.0f;
            #pragma unroll
            for (int off = 16; off > 0; off >>= 1)
                sq += __shfl_xor_sync(0xffffffffu, sq, off);
            float rinv = rsqrtf(sq);
            if (t < NDIM) v[t] = w[t] * rinv;
        } else {
            if (t < NDIM) v[t] = w[t];
        }
        __syncthreads();
    }

    float s = 0.0f;
    if (t < NDIM) {
        #pragma unroll
        for (int k = 0; k < NDIM; k++) s += Ps[t * NDIM + k] * v[k];
    }
    float num = (t < NDIM) ? v[t] * s : 0.0f;
    float den = (t < NDIM) ? v[t] * v[t] : 0.0f;
    #pragma unroll
    for (int off = 16; off > 0; off >>= 1) {
        num += __shfl_xor_sync(0xffffffffu, num, off);
        den += __shfl_xor_sync(0xffffffffu, den, off);
    }
    const float step = den / num;  // 1 / lambda_max
    if (t == 0) g_step = step;

    for (int i = t; i < NDIM * NDIM; i += 32) {
        int r = i / NDIM, c = i % NDIM;
        g_A[i] = ((r == c) ? 1.0f : 0.0f) - step * Ps[i];
    }
}

// ---------------------------------------------------------------------------
// Solver: 2 rows per thread, single-warp CTAs. Two independent iteration
// chains interleave to fill latency; each constant-cache A read feeds both.
// b in per-thread smem slots (no syncs needed: one warp, own slot only).
// ---------------------------------------------------------------------------
__global__ void __launch_bounds__(TPB)
solve_kernel(const float* __restrict__ q, float* __restrict__ out) {
    __shared__ unsigned long long Bsh[RPT][12][TPB];

    const int tid  = threadIdx.x;
    const int row0 = blockIdx.x * (TPB * RPT) + tid;   // second row = row0 + TPB
    const float stepv = g_step;

    #pragma unroll
    for (int r = 0; r < RPT; r++) {
        const float4* q4 =
            reinterpret_cast<const float4*>(q + (size_t)(row0 + r * TPB) * NDIM);
        #pragma unroll
        for (int i = 0; i < 6; i++) {
            float4 v = q4[i];
            Bsh[r][2 * i + 0][tid] = pack2(-stepv * v.x, -stepv * v.y);
            Bsh[r][2 * i + 1][tid] = pack2(-stepv * v.z, -stepv * v.w);
        }
    }

    // Peel iteration 1: l = proj(b)  (l0 = 0)
    float lA[NDIM], lB[NDIM];
    {
        unsigned long long t0[12], t1[12];
        #pragma unroll
        for (int jp = 0; jp < 12; jp++) { t0[jp] = Bsh[0][jp][tid]; t1[jp] = Bsh[1][jp][tid]; }
        proj_soc(t0, lA);
        proj_soc(t1, lB);
    }

    #pragma unroll 1
    for (int it = 1; it < NITERS; it++) {
        unsigned long long accA[12], accB[12];
        // k = 0 folds acc init: acc = l0 * A_row0 + b
        {
            const unsigned long long lkA = pack2(lA[0], lA[0]);
            const unsigned long long lkB = pack2(lB[0], lB[0]);
            const float4* Ar = reinterpret_cast<const float4*>(&c_A[0]);
            #pragma unroll
            for (int m = 0; m < 6; m++) {
                float4 a = Ar[m];
                unsigned long long p0 = pack2(a.x, a.y);
                unsigned long long p1 = pack2(a.z, a.w);
                accA[2 * m + 0] = fma2(lkA, p0, Bsh[0][2 * m + 0][tid]);
                accA[2 * m + 1] = fma2(lkA, p1, Bsh[0][2 * m + 1][tid]);
                accB[2 * m + 0] = fma2(lkB, p0, Bsh[1][2 * m + 0][tid]);
                accB[2 * m + 1] = fma2(lkB, p1, Bsh[1][2 * m + 1][tid]);
            }
        }
        #pragma unroll
        for (int k = 1; k < NDIM; k++) {
            const unsigned long long lkA = pack2(lA[k], lA[k]);
            const unsigned long long lkB = pack2(lB[k], lB[k]);
            const float4* Ar = reinterpret_cast<const float4*>(&c_A[k * NDIM]);
            #pragma unroll
            for (int m = 0; m < 6; m++) {
                float4 a = Ar[m];
                unsigned long long p0 = pack2(a.x, a.y);
                unsigned long long p1 = pack2(a.z, a.w);
                accA[2 * m + 0] = fma2(lkA, p0, accA[2 * m + 0]);
                accA[2 * m + 1] = fma2(lkA, p1, accA[2 * m + 1]);
                accB[2 * m + 0] = fma2(lkB, p0, accB[2 * m + 0]);
                accB[2 * m + 1] = fma2(lkB, p1, accB[2 * m + 1]);
            }
        }
        proj_soc(accA, lA);
        proj_soc(accB, lB);
    }

    {
        float4* o4 = reinterpret_cast<float4*>(out + (size_t)row0 * NDIM);
        #pragma unroll
        for (int i = 0; i < 6; i++)
            o4[i] = make_float4(lA[4 * i + 0], lA[4 * i + 1], lA[4 * i + 2], lA[4 * i + 3]);
    }
    {
        float4* o4 = reinterpret_cast<float4*>(out + (size_t)(row0 + TPB) * NDIM);
        #pragma unroll
        for (int i = 0; i < 6; i++)
            o4[i] = make_float4(lB[4 * i + 0], lB[4 * i + 1], lB[4 * i + 2], lB[4 * i + 3]);
    }
}

// ---------------------------------------------------------------------------
// Entry point (graph-capturable: kernels + D2D memcpy only)
// ---------------------------------------------------------------------------
extern "C" void kernel_launch(void* const* d_in, const int* in_sizes, int n_in,
                              void* d_out, int out_size) {
    const float* P = (const float*)d_in[0];   // (1, 24, 24) fp32
    const float* q = (const float*)d_in[1];   // (65536, 24, 1) fp32
    float* out = (float*)d_out;               // (65536, 24) fp32

    prep_kernel<<<1, 32>>>(P);

    void* gA_ptr = nullptr;
    cudaGetSymbolAddress(&gA_ptr, g_A);
    cudaMemcpyToSymbolAsync(c_A, gA_ptr, NDIM * NDIM * sizeof(float), 0,
                            cudaMemcpyDeviceToDevice, 0);

    solve_kernel<<<BATCH / (TPB * RPT), TPB>>>(q, out);
}